// round 2
// baseline (speedup 1.0000x reference)
#include <cuda_runtime.h>
#include <math.h>

#define BB 128
#define TT 256
#define HH 512
#define H3 1536

// ---------------- scratch (module globals: allowed; no cudaMalloc) ----------
__device__ float g_xp[(size_t)BB * TT * H3];   // per-layer input projections (201 MB)
__device__ float g_y [(size_t)BB * TT * HH];   // inter-layer sequence buffer (67 MB)
__device__ float g_h [2][BB * HH];             // ping-pong hidden state
__device__ unsigned g_bar[4];                  // per-batch-group barrier counters

// ---------------- init: zero h0 and barrier counters (every replay) ---------
__global__ void init_k() {
    int i = blockIdx.x * blockDim.x + threadIdx.x;
    if (i < BB * HH) g_h[0][i] = 0.0f;
    if (i < 4) g_bar[i] = 0u;
}

// ---------------- input projection: g_xp = Ain @ Wk + b0 --------------------
// M=B*T=32768, N=3H=1536, K=H=512. 64x64 tile, BK=16, 256 threads, 4x4 micro.
__global__ void __launch_bounds__(256) proj_k(const float* __restrict__ xin,
                                              const float* __restrict__ Wk,
                                              const float* __restrict__ bias,
                                              int useY)
{
    const float* Ain = useY ? (const float*)g_y : xin;
    __shared__ float As[16 * 68];   // As[k][m], padded rows (16B aligned)
    __shared__ float Bs[16 * 68];   // Bs[k][n]
    const int tid = threadIdx.x;
    const int m0 = blockIdx.y * 64;
    const int n0 = blockIdx.x * 64;
    const int tx = tid & 15, ty = tid >> 4;
    const int mA = tid >> 2, kA = (tid & 3) << 2;
    const int kB = tid >> 4, nB = (tid & 15) << 2;
    const float* aptr = Ain + (size_t)(m0 + mA) * HH + kA;
    const float* bptr = Wk + (size_t)kB * H3 + n0 + nB;

    float acc[4][4] = {};
    for (int kt = 0; kt < HH / 16; ++kt) {
        float4 av = *(const float4*)(aptr + kt * 16);
        float4 bv = *(const float4*)(bptr + (size_t)(kt * 16) * H3);
        __syncthreads();
        As[(kA + 0) * 68 + mA] = av.x;
        As[(kA + 1) * 68 + mA] = av.y;
        As[(kA + 2) * 68 + mA] = av.z;
        As[(kA + 3) * 68 + mA] = av.w;
        *(float4*)&Bs[kB * 68 + nB] = bv;
        __syncthreads();
#pragma unroll
        for (int k = 0; k < 16; ++k) {
            float4 a4 = *(const float4*)&As[k * 68 + (ty << 2)];
            float4 b4 = *(const float4*)&Bs[k * 68 + (tx << 2)];
            float aa[4] = {a4.x, a4.y, a4.z, a4.w};
            float bb[4] = {b4.x, b4.y, b4.z, b4.w};
#pragma unroll
            for (int i = 0; i < 4; ++i)
#pragma unroll
                for (int j = 0; j < 4; ++j)
                    acc[i][j] += aa[i] * bb[j];
        }
    }
    float4 b4 = *(const float4*)&bias[n0 + (tx << 2)];
    float bbv[4] = {b4.x, b4.y, b4.z, b4.w};
#pragma unroll
    for (int i = 0; i < 4; ++i) {
        int row = m0 + (ty << 2) + i;
        float4 o;
        o.x = acc[i][0] + bbv[0];
        o.y = acc[i][1] + bbv[1];
        o.z = acc[i][2] + bbv[2];
        o.w = acc[i][3] + bbv[3];
        *(float4*)&g_xp[(size_t)row * H3 + n0 + (tx << 2)] = o;
    }
}

// ---------------- persistent recurrent kernel (one per layer) ---------------
// Grid: 128 CTAs = 4 batch-groups (32 batches) x 32 h-groups (16 h-cols).
// Each CTA keeps its Wu slice [512][48] in smem for all 256 steps.
// Per step: group barrier -> stage h slice -> 32x48 GEMM -> gates -> write h/y.
#define SM_WS   (512 * 48)        // weights  (24576 floats)
#define SM_HS   (32 * 513)        // staged h (padded rows)
#define SM_RECS (32 * 49)         // rec pre-activations
#define SM_BRS  48
#define SMEM_FLOATS (SM_WS + SM_HS + SM_RECS + SM_BRS)

__global__ void __launch_bounds__(128, 1) gru_layer_k(const float* __restrict__ Wu,
                                                      const float* __restrict__ br,
                                                      float* __restrict__ dout,
                                                      int layer, int isLast)
{
    extern __shared__ float sm[];
    float* ws   = sm;                       // [k][j], j = gate*16 + cc
    float* hs   = ws + SM_WS;               // [b][k] (row stride 513)
    float* recs = hs + SM_HS;               // [b][j] (row stride 49)
    float* brs  = recs + SM_RECS;

    const int tid = threadIdx.x;
    const int g   = blockIdx.x >> 5;        // batch group 0..3
    const int hg  = blockIdx.x & 31;        // h group 0..31
    const int b0g = g * 32;
    const int c0g = hg * 16;

    // one-time: load Wu slice + recurrent bias slice into smem
    for (int idx = tid; idx < SM_WS; idx += 128) {
        int k = idx / 48, j = idx % 48;
        int gate = j >> 4, cc = j & 15;
        ws[idx] = Wu[(size_t)k * H3 + gate * HH + c0g + cc];
    }
    for (int j = tid; j < 48; j += 128) {
        int gate = j >> 4, cc = j & 15;
        brs[j] = br[gate * HH + c0g + cc];
    }
    __syncthreads();

    const int rt = tid & 7, ct = tid >> 3;   // 8 x 16 thread grid
    const int r0 = rt * 4;                   // 4 batch rows / thread
    const int c0 = ct * 3;                   // 3 cols / thread
    const unsigned layerBase = (unsigned)layer * TT;

    for (int t = 0; t < TT; ++t) {
        // ---- inter-CTA barrier (per batch group, monotonic counter) ----
        unsigned target = 32u * (layerBase + (unsigned)t);
        if (tid == 0) {
            while (*(volatile unsigned*)&g_bar[g] < target) { }
        }
        __syncthreads();
        __threadfence();

        // ---- stage h[b0g..b0g+31][0..511] into smem (L2 reads, L1 stale) ----
        const float* hsrc = g_h[t & 1];
        for (int it = tid; it < 4096; it += 128) {
            int b = it >> 7, kq = it & 127;
            float4 v = __ldcg((const float4*)&hsrc[(size_t)(b0g + b) * HH + (kq << 2)]);
            int base = b * 513 + (kq << 2);
            hs[base + 0] = v.x; hs[base + 1] = v.y;
            hs[base + 2] = v.z; hs[base + 3] = v.w;
        }
        __syncthreads();

        // ---- GEMM: rec[32][48] = h[32][512] @ ws[512][48] ----
        float acc[4][3] = {};
#pragma unroll 8
        for (int k = 0; k < 512; ++k) {
            float w0 = ws[k * 48 + c0 + 0];
            float w1 = ws[k * 48 + c0 + 1];
            float w2 = ws[k * 48 + c0 + 2];
#pragma unroll
            for (int i = 0; i < 4; ++i) {
                float a = hs[(r0 + i) * 513 + k];
                acc[i][0] += a * w0;
                acc[i][1] += a * w1;
                acc[i][2] += a * w2;
            }
        }
#pragma unroll
        for (int i = 0; i < 4; ++i)
#pragma unroll
            for (int j = 0; j < 3; ++j)
                recs[(r0 + i) * 49 + c0 + j] = acc[i][j] + brs[c0 + j];
        __syncthreads();

        // ---- gates + state update for this CTA's 32x16 elements ----
        float* hdst = g_h[(t + 1) & 1];
        float* yout = isLast ? dout : (float*)g_y;
        for (int idx = tid; idx < 512; idx += 128) {
            int b = idx >> 4, c = idx & 15;
            int gb = b0g + b, gc = c0g + c;
            size_t xb = ((size_t)gb * TT + t) * H3;
            float xz = g_xp[xb + gc];
            float xr = g_xp[xb + HH + gc];
            float xh = g_xp[xb + 2 * HH + gc];
            float rz = recs[b * 49 + c];
            float rr = recs[b * 49 + 16 + c];
            float rh = recs[b * 49 + 32 + c];
            float z = 1.0f / (1.0f + expf(-(xz + rz)));
            float r = 1.0f / (1.0f + expf(-(xr + rr)));
            float hh = tanhf(xh + r * rh);
            float hold = hs[b * 513 + gc];
            float hn = z * hold + (1.0f - z) * hh;
            hdst[(size_t)gb * HH + gc] = hn;
            yout[((size_t)gb * TT + t) * HH + gc] = hn;
        }

        // ---- arrive ----
        __threadfence();
        __syncthreads();
        if (tid == 0) atomicAdd(&g_bar[g], 1u);
    }
}

// ---------------- final state copy -------------------------------------------
__global__ void copy_h_k(float* dout, int out_size) {
    int i = blockIdx.x * blockDim.x + threadIdx.x;
    size_t off = (size_t)BB * TT * HH;
    if (i < BB * HH && (off + i) < (size_t)out_size)
        dout[off + i] = g_h[0][i];
}

// ---------------- launch ------------------------------------------------------
extern "C" void kernel_launch(void* const* d_in, const int* in_sizes, int n_in,
                              void* d_out, int out_size) {
    const float* x        = (const float*)d_in[0];   // [B,T,H]
    const float* kernels  = (const float*)d_in[1];   // [L,H,3H]
    const float* rkernels = (const float*)d_in[2];   // [L,H,3H]
    const float* biases   = (const float*)d_in[3];   // [L,2,3H]
    float* out = (float*)d_out;

    cudaFuncSetAttribute(gru_layer_k, cudaFuncAttributeMaxDynamicSharedMemorySize,
                         SMEM_FLOATS * (int)sizeof(float));

    init_k<<<(BB * HH + 255) / 256, 256>>>();

    dim3 pgrid(H3 / 64, (BB * TT) / 64);
    for (int l = 0; l < 3; ++l) {
        proj_k<<<pgrid, 256>>>(x,
                               kernels + (size_t)l * HH * H3,
                               biases + (size_t)l * 2 * H3,
                               l > 0);
        gru_layer_k<<<128, 128, SMEM_FLOATS * (int)sizeof(float)>>>(
            rkernels + (size_t)l * HH * H3,
            biases + (size_t)l * 2 * H3 + H3,
            out, l, (l == 2) ? 1 : 0);
    }
    copy_h_k<<<(BB * HH + 255) / 256, 256>>>(out, out_size);
}

// round 5
// speedup vs baseline: 1.6375x; 1.6375x over previous
#include <cuda_runtime.h>
#include <math.h>

#define BB 128
#define TT 256
#define HH 512
#define H3 1536
typedef unsigned long long ull;

__device__ __forceinline__ ull dup2(float x) {
    ull r; asm("mov.b64 %0, {%1, %1};" : "=l"(r) : "f"(x)); return r;
}
__device__ __forceinline__ void ffma2(ull& d, ull a, ull b) {
    asm("fma.rn.f32x2 %0, %1, %2, %0;" : "+l"(d) : "l"(a), "l"(b));
}
__device__ __forceinline__ float2 unpk(ull v) {
    float2 f; asm("mov.b64 {%0, %1}, %2;" : "=f"(f.x), "=f"(f.y) : "l"(v)); return f;
}

__device__ float g_xp[(size_t)BB * TT * H3];
__device__ float g_y [(size_t)BB * TT * HH];
__device__ float g_h [2][BB * HH];
__device__ unsigned g_bar[4];

__global__ void init_k() {
    int i = blockIdx.x * blockDim.x + threadIdx.x;
    if (i < BB * HH) g_h[0][i] = 0.0f;
    if (i < 4) g_bar[i] = 0u;
}

// ---- proj: g_xp = Ain @ Wk + b0 (FFMA2, tile 128x64, BK=16) ----------------
__global__ void __launch_bounds__(256) proj_k(const float* __restrict__ xin,
                                              const float* __restrict__ Wk,
                                              const float* __restrict__ bias,
                                              int useY)
{
    const float* Ain = useY ? (const float*)g_y : xin;
    __shared__ float As[16 * 128];
    __shared__ float Bs[16 * 64];
    const int tid = threadIdx.x;
    const int m0 = blockIdx.y * 128, n0 = blockIdx.x * 64;
    const int tx = tid & 15, ty = tid >> 4;
    const int my = ty * 8;
    const int mA = tid >> 1, kA = (tid & 1) * 8;
    const int kB = tid >> 4, nB = (tid & 15) * 4;
    const float* aptr = Ain + (size_t)(m0 + mA) * HH + kA;
    const float* bptr = Wk + (size_t)kB * H3 + n0 + nB;

    ull acc[4][4];
#pragma unroll
    for (int p = 0; p < 4; ++p)
#pragma unroll
        for (int j = 0; j < 4; ++j) acc[p][j] = 0ull;

    for (int kt = 0; kt < HH / 16; ++kt) {
        float4 av0 = *(const float4*)(aptr + kt * 16);
        float4 av1 = *(const float4*)(aptr + kt * 16 + 4);
        float4 bv  = *(const float4*)(bptr + (size_t)(kt * 16) * H3);
        __syncthreads();
        As[(kA + 0) * 128 + mA] = av0.x; As[(kA + 1) * 128 + mA] = av0.y;
        As[(kA + 2) * 128 + mA] = av0.z; As[(kA + 3) * 128 + mA] = av0.w;
        As[(kA + 4) * 128 + mA] = av1.x; As[(kA + 5) * 128 + mA] = av1.y;
        As[(kA + 6) * 128 + mA] = av1.z; As[(kA + 7) * 128 + mA] = av1.w;
        *(float4*)&Bs[kB * 64 + nB] = bv;
        __syncthreads();
#pragma unroll
        for (int k = 0; k < 16; ++k) {
            const ull* ap = (const ull*)(As + k * 128 + my);
            ull A0 = ap[0], A1 = ap[1], A2 = ap[2], A3 = ap[3];
            float4 w4 = *(const float4*)(Bs + k * 64 + tx * 4);
            ull W0 = dup2(w4.x), W1 = dup2(w4.y), W2 = dup2(w4.z), W3 = dup2(w4.w);
            ffma2(acc[0][0], A0, W0); ffma2(acc[0][1], A0, W1);
            ffma2(acc[0][2], A0, W2); ffma2(acc[0][3], A0, W3);
            ffma2(acc[1][0], A1, W0); ffma2(acc[1][1], A1, W1);
            ffma2(acc[1][2], A1, W2); ffma2(acc[1][3], A1, W3);
            ffma2(acc[2][0], A2, W0); ffma2(acc[2][1], A2, W1);
            ffma2(acc[2][2], A2, W2); ffma2(acc[2][3], A2, W3);
            ffma2(acc[3][0], A3, W0); ffma2(acc[3][1], A3, W1);
            ffma2(acc[3][2], A3, W2); ffma2(acc[3][3], A3, W3);
        }
    }
    float4 b4 = *(const float4*)&bias[n0 + tx * 4];
    float bb[4] = {b4.x, b4.y, b4.z, b4.w};
#pragma unroll
    for (int p = 0; p < 4; ++p) {
        float2 u0 = unpk(acc[p][0]), u1 = unpk(acc[p][1]);
        float2 u2 = unpk(acc[p][2]), u3 = unpk(acc[p][3]);
        int rlo = m0 + my + 2 * p;
        float4 o0 = {u0.x + bb[0], u1.x + bb[1], u2.x + bb[2], u3.x + bb[3]};
        float4 o1 = {u0.y + bb[0], u1.y + bb[1], u2.y + bb[2], u3.y + bb[3]};
        *(float4*)&g_xp[(size_t)rlo * H3 + n0 + tx * 4] = o0;
        *(float4*)&g_xp[(size_t)(rlo + 1) * H3 + n0 + tx * 4] = o1;
    }
}

// ---- gru: split-K by warp, FFMA2, fixed full-coverage staging ---------------
#define SM_WS   (512 * 48)
#define SM_HS   (32 * 513)
#define SM_RP   (4 * 32 * 49)
#define SMEM_FLOATS (SM_WS + SM_HS + SM_RP + 48)

__global__ void __launch_bounds__(128, 1) gru_layer_k(const float* __restrict__ Wu,
                                                      const float* __restrict__ br,
                                                      float* __restrict__ dout,
                                                      int layer, int isLast)
{
    extern __shared__ float sm[];
    float* ws  = sm;              // [k][j], j = gate*16+cc
    float* hs  = ws + SM_WS;      // [b][k], stride 513
    float* rp  = hs + SM_HS;      // [warp][b][j], stride 49
    float* brs = rp + SM_RP;

    const int tid = threadIdx.x;
    const int g   = blockIdx.x >> 5;
    const int hg  = blockIdx.x & 31;
    const int b0g = g * 32, c0g = hg * 16;

    for (int idx = tid; idx < SM_WS; idx += 128) {
        int k = idx / 48, j = idx % 48;
        ws[idx] = Wu[(size_t)k * H3 + (j >> 4) * HH + c0g + (j & 15)];
    }
    for (int j = tid; j < 48; j += 128)
        brs[j] = br[(j >> 4) * HH + c0g + (j & 15)];
    __syncthreads();

    const int wrp = tid >> 5, lane = tid & 31;
    const int r0 = (lane & 7) * 4;          // 4 batch rows / thread
    const int c0 = (lane >> 3) * 12;        // 12 cols / thread (6 f32x2)
    const int kbase = wrp * 128;
    const unsigned layerBase = (unsigned)layer * TT;

    for (int t = 0; t < TT; ++t) {
        // xp prefetch (barrier-independent)
        float pz[4], pr[4], ph[4];
#pragma unroll
        for (int q = 0; q < 4; ++q) {
            int idx = tid + q * 128;
            const float* xb = g_xp + ((size_t)(b0g + (idx >> 4)) * TT + t) * H3
                              + (c0g + (idx & 15));
            pz[q] = __ldcs(xb); pr[q] = __ldcs(xb + HH); ph[q] = __ldcs(xb + 2 * HH);
        }

        unsigned target = 32u * (layerBase + (unsigned)t);
        if (tid == 0) { while (*(volatile unsigned*)&g_bar[g] < target) { } }
        __syncthreads();
        __threadfence();

        // stage h[32][512] — FULL coverage: 32 float4 loads/thread (round-1 form)
        const float* hsrc = g_h[t & 1];
#pragma unroll
        for (int u = 0; u < 32; ++u) {
            int it = tid + u * 128;
            int b = it >> 7, kq = it & 127;
            float4 v = __ldcg((const float4*)&hsrc[(size_t)(b0g + b) * HH + (kq << 2)]);
            int base = b * 513 + (kq << 2);
            hs[base + 0] = v.x; hs[base + 1] = v.y;
            hs[base + 2] = v.z; hs[base + 3] = v.w;
        }
        __syncthreads();

        // split-K GEMM: this warp's 128-k slice of rec[32][48]
        ull acc[4][6];
#pragma unroll
        for (int i = 0; i < 4; ++i)
#pragma unroll
            for (int q = 0; q < 6; ++q) acc[i][q] = 0ull;
#pragma unroll 4
        for (int kk = 0; kk < 128; ++kk) {
            int k = kbase + kk;
            const float* hk = hs + k;
            ull A0 = dup2(hk[(r0 + 0) * 513]);
            ull A1 = dup2(hk[(r0 + 1) * 513]);
            ull A2 = dup2(hk[(r0 + 2) * 513]);
            ull A3 = dup2(hk[(r0 + 3) * 513]);
            const ull* wv = (const ull*)(ws + k * 48 + c0);
            ull w0 = wv[0], w1 = wv[1], w2 = wv[2], w3 = wv[3], w4 = wv[4], w5 = wv[5];
            ffma2(acc[0][0], A0, w0); ffma2(acc[0][1], A0, w1); ffma2(acc[0][2], A0, w2);
            ffma2(acc[0][3], A0, w3); ffma2(acc[0][4], A0, w4); ffma2(acc[0][5], A0, w5);
            ffma2(acc[1][0], A1, w0); ffma2(acc[1][1], A1, w1); ffma2(acc[1][2], A1, w2);
            ffma2(acc[1][3], A1, w3); ffma2(acc[1][4], A1, w4); ffma2(acc[1][5], A1, w5);
            ffma2(acc[2][0], A2, w0); ffma2(acc[2][1], A2, w1); ffma2(acc[2][2], A2, w2);
            ffma2(acc[2][3], A2, w3); ffma2(acc[2][4], A2, w4); ffma2(acc[2][5], A2, w5);
            ffma2(acc[3][0], A3, w0); ffma2(acc[3][1], A3, w1); ffma2(acc[3][2], A3, w2);
            ffma2(acc[3][3], A3, w3); ffma2(acc[3][4], A3, w4); ffma2(acc[3][5], A3, w5);
        }
        float* rpw = rp + wrp * (32 * 49);
#pragma unroll
        for (int i = 0; i < 4; ++i)
#pragma unroll
            for (int q = 0; q < 6; ++q) {
                float2 u = unpk(acc[i][q]);
                rpw[(r0 + i) * 49 + c0 + 2 * q]     = u.x;
                rpw[(r0 + i) * 49 + c0 + 2 * q + 1] = u.y;
            }
        __syncthreads();

        // reduce partials + gates + state update
        float* hdst = g_h[(t + 1) & 1];
        float* yout = isLast ? dout : (float*)g_y;
#pragma unroll
        for (int q = 0; q < 4; ++q) {
            int idx = tid + q * 128;
            int b = idx >> 4, c = idx & 15;
            int gb = b0g + b, gc = c0g + c;
            int base = b * 49;
            float rz = rp[base + c] + rp[1568 + base + c]
                     + rp[3136 + base + c] + rp[4704 + base + c] + brs[c];
            float rr = rp[base + 16 + c] + rp[1568 + base + 16 + c]
                     + rp[3136 + base + 16 + c] + rp[4704 + base + 16 + c] + brs[16 + c];
            float rh = rp[base + 32 + c] + rp[1568 + base + 32 + c]
                     + rp[3136 + base + 32 + c] + rp[4704 + base + 32 + c] + brs[32 + c];
            float z = 1.0f / (1.0f + expf(-(pz[q] + rz)));
            float r = 1.0f / (1.0f + expf(-(pr[q] + rr)));
            float hh = tanhf(ph[q] + r * rh);
            float hold = hs[b * 513 + gc];
            float hn = z * hold + (1.0f - z) * hh;
            hdst[(size_t)gb * HH + gc] = hn;
            yout[((size_t)gb * TT + t) * HH + gc] = hn;
        }

        __threadfence();
        __syncthreads();
        if (tid == 0) atomicAdd(&g_bar[g], 1u);
    }
}

__global__ void copy_h_k(float* dout, int out_size) {
    int i = blockIdx.x * blockDim.x + threadIdx.x;
    size_t off = (size_t)BB * TT * HH;
    if (i < BB * HH && (off + i) < (size_t)out_size)
        dout[off + i] = g_h[0][i];
}

extern "C" void kernel_launch(void* const* d_in, const int* in_sizes, int n_in,
                              void* d_out, int out_size) {
    const float* x        = (const float*)d_in[0];
    const float* kernels  = (const float*)d_in[1];
    const float* rkernels = (const float*)d_in[2];
    const float* biases   = (const float*)d_in[3];
    float* out = (float*)d_out;

    cudaFuncSetAttribute(gru_layer_k, cudaFuncAttributeMaxDynamicSharedMemorySize,
                         SMEM_FLOATS * (int)sizeof(float));
    init_k<<<(BB * HH + 255) / 256, 256>>>();

    dim3 pgrid(H3 / 64, (BB * TT) / 128);
    for (int l = 0; l < 3; ++l) {
        proj_k<<<pgrid, 256>>>(x, kernels + (size_t)l * HH * H3,
                               biases + (size_t)l * 2 * H3, l > 0);
        gru_layer_k<<<128, 128, SMEM_FLOATS * (int)sizeof(float)>>>(
            rkernels + (size_t)l * HH * H3,
            biases + (size_t)l * 2 * H3 + H3,
            out, l, (l == 2) ? 1 : 0);
    }
    copy_h_k<<<(BB * HH + 255) / 256, 256>>>(out, out_size);
}

// round 6
// speedup vs baseline: 1.6548x; 1.0106x over previous
#include <cuda_runtime.h>
#include <math.h>

#define BB 128
#define TT 256
#define HH 512
#define H3 1536
typedef unsigned long long ull;

__device__ __forceinline__ ull dup2(float x) {
    ull r; asm("mov.b64 %0, {%1, %1};" : "=l"(r) : "f"(x)); return r;
}
__device__ __forceinline__ void ffma2(ull& d, ull a, ull b) {
    asm("fma.rn.f32x2 %0, %1, %2, %0;" : "+l"(d) : "l"(a), "l"(b));
}
__device__ __forceinline__ float2 unpk(ull v) {
    float2 f; asm("mov.b64 {%0, %1}, %2;" : "=f"(f.x), "=f"(f.y) : "l"(v)); return f;
}

__device__ float g_xp[(size_t)BB * TT * H3];
__device__ float g_y [(size_t)BB * TT * HH];
__device__ float g_h [2][BB * HH];
__device__ unsigned g_bar[4];

__global__ void init_k() {
    int i = blockIdx.x * blockDim.x + threadIdx.x;
    if (i < BB * HH) g_h[0][i] = 0.0f;
    if (i < 4) g_bar[i] = 0u;
}

// ---- proj: g_xp = Ain @ Wk + b0 (FFMA2, tile 128x64, BK=16, 4 CTA/SM) ------
__global__ void __launch_bounds__(256, 4) proj_k(const float* __restrict__ xin,
                                                 const float* __restrict__ Wk,
                                                 const float* __restrict__ bias,
                                                 int useY)
{
    const float* Ain = useY ? (const float*)g_y : xin;
    __shared__ float As[16 * 128];
    __shared__ float Bs[16 * 64];
    const int tid = threadIdx.x;
    const int m0 = blockIdx.y * 128, n0 = blockIdx.x * 64;
    const int tx = tid & 15, ty = tid >> 4;
    const int my = ty * 8;
    const int mA = tid >> 1, kA = (tid & 1) * 8;
    const int kB = tid >> 4, nB = (tid & 15) * 4;
    const float* aptr = Ain + (size_t)(m0 + mA) * HH + kA;
    const float* bptr = Wk + (size_t)kB * H3 + n0 + nB;

    ull acc[4][4];
#pragma unroll
    for (int p = 0; p < 4; ++p)
#pragma unroll
        for (int j = 0; j < 4; ++j) acc[p][j] = 0ull;

    for (int kt = 0; kt < HH / 16; ++kt) {
        float4 av0 = *(const float4*)(aptr + kt * 16);
        float4 av1 = *(const float4*)(aptr + kt * 16 + 4);
        float4 bv  = *(const float4*)(bptr + (size_t)(kt * 16) * H3);
        __syncthreads();
        As[(kA + 0) * 128 + mA] = av0.x; As[(kA + 1) * 128 + mA] = av0.y;
        As[(kA + 2) * 128 + mA] = av0.z; As[(kA + 3) * 128 + mA] = av0.w;
        As[(kA + 4) * 128 + mA] = av1.x; As[(kA + 5) * 128 + mA] = av1.y;
        As[(kA + 6) * 128 + mA] = av1.z; As[(kA + 7) * 128 + mA] = av1.w;
        *(float4*)&Bs[kB * 64 + nB] = bv;
        __syncthreads();
#pragma unroll
        for (int k = 0; k < 16; ++k) {
            const ull* ap = (const ull*)(As + k * 128 + my);
            ull A0 = ap[0], A1 = ap[1], A2 = ap[2], A3 = ap[3];
            float4 w4 = *(const float4*)(Bs + k * 64 + tx * 4);
            ull W0 = dup2(w4.x), W1 = dup2(w4.y), W2 = dup2(w4.z), W3 = dup2(w4.w);
            ffma2(acc[0][0], A0, W0); ffma2(acc[0][1], A0, W1);
            ffma2(acc[0][2], A0, W2); ffma2(acc[0][3], A0, W3);
            ffma2(acc[1][0], A1, W0); ffma2(acc[1][1], A1, W1);
            ffma2(acc[1][2], A1, W2); ffma2(acc[1][3], A1, W3);
            ffma2(acc[2][0], A2, W0); ffma2(acc[2][1], A2, W1);
            ffma2(acc[2][2], A2, W2); ffma2(acc[2][3], A2, W3);
            ffma2(acc[3][0], A3, W0); ffma2(acc[3][1], A3, W1);
            ffma2(acc[3][2], A3, W2); ffma2(acc[3][3], A3, W3);
        }
    }
    float4 b4 = *(const float4*)&bias[n0 + tx * 4];
    float bb[4] = {b4.x, b4.y, b4.z, b4.w};
#pragma unroll
    for (int p = 0; p < 4; ++p) {
        float2 u0 = unpk(acc[p][0]), u1 = unpk(acc[p][1]);
        float2 u2 = unpk(acc[p][2]), u3 = unpk(acc[p][3]);
        int rlo = m0 + my + 2 * p;
        float4 o0 = {u0.x + bb[0], u1.x + bb[1], u2.x + bb[2], u3.x + bb[3]};
        float4 o1 = {u0.y + bb[0], u1.y + bb[1], u2.y + bb[2], u3.y + bb[3]};
        *(float4*)&g_xp[(size_t)rlo * H3 + n0 + tx * 4] = o0;
        *(float4*)&g_xp[(size_t)(rlo + 1) * H3 + n0 + tx * 4] = o1;
    }
}

// ---- gru: 8-warp split-K, FFMA2, LDS.128 weight loads ------------------------
#define SM_WS   (512 * 48)
#define SM_HS   (32 * 513)
#define SM_RP   (8 * 32 * 49)
#define SMEM_FLOATS (SM_WS + SM_HS + SM_RP + 48)

__global__ void __launch_bounds__(256, 1) gru_layer_k(const float* __restrict__ Wu,
                                                      const float* __restrict__ br,
                                                      float* __restrict__ dout,
                                                      int layer, int isLast)
{
    extern __shared__ float sm[];
    float* ws  = sm;              // [k][j], j = gate*16+cc
    float* hs  = ws + SM_WS;      // [b][k], stride 513
    float* rp  = hs + SM_HS;      // [warp][b][j], stride 49
    float* brs = rp + SM_RP;

    const int tid = threadIdx.x;
    const int g   = blockIdx.x >> 5;
    const int hg  = blockIdx.x & 31;
    const int b0g = g * 32, c0g = hg * 16;

    for (int idx = tid; idx < SM_WS; idx += 256) {
        int k = idx / 48, j = idx % 48;
        ws[idx] = Wu[(size_t)k * H3 + (j >> 4) * HH + c0g + (j & 15)];
    }
    for (int j = tid; j < 48; j += 256)
        brs[j] = br[(j >> 4) * HH + c0g + (j & 15)];
    __syncthreads();

    const int wrp = tid >> 5, lane = tid & 31;
    const int r0 = (lane & 7) * 4;          // 4 batch rows / thread
    const int c0 = (lane >> 3) * 12;        // 12 cols / thread (6 f32x2)
    const int kbase = wrp * 64;             // 8 warps x 64-k slices
    const unsigned layerBase = (unsigned)layer * TT;

    for (int t = 0; t < TT; ++t) {
        // xp prefetch (barrier-independent)
        float pz[2], pr[2], ph[2];
#pragma unroll
        for (int q = 0; q < 2; ++q) {
            int idx = tid + q * 256;
            const float* xb = g_xp + ((size_t)(b0g + (idx >> 4)) * TT + t) * H3
                              + (c0g + (idx & 15));
            pz[q] = __ldcs(xb); pr[q] = __ldcs(xb + HH); ph[q] = __ldcs(xb + 2 * HH);
        }

        unsigned target = 32u * (layerBase + (unsigned)t);
        if (tid == 0) { while (*(volatile unsigned*)&g_bar[g] < target) { } }
        __syncthreads();
        __threadfence();

        // stage h[32][512]: 16 float4 loads/thread, full coverage
        const float* hsrc = g_h[t & 1];
#pragma unroll
        for (int u = 0; u < 16; ++u) {
            int it = tid + u * 256;
            int b = it >> 7, kq = it & 127;
            float4 v = __ldcg((const float4*)&hsrc[(size_t)(b0g + b) * HH + (kq << 2)]);
            int base = b * 513 + (kq << 2);
            hs[base + 0] = v.x; hs[base + 1] = v.y;
            hs[base + 2] = v.z; hs[base + 3] = v.w;
        }
        __syncthreads();

        // split-K GEMM: this warp's 64-k slice of rec[32][48]
        ull acc[4][6];
#pragma unroll
        for (int i = 0; i < 4; ++i)
#pragma unroll
            for (int q = 0; q < 6; ++q) acc[i][q] = 0ull;
#pragma unroll 4
        for (int kk = 0; kk < 64; ++kk) {
            int k = kbase + kk;
            const float* hk = hs + k;
            ull A0 = dup2(hk[(r0 + 0) * 513]);
            ull A1 = dup2(hk[(r0 + 1) * 513]);
            ull A2 = dup2(hk[(r0 + 2) * 513]);
            ull A3 = dup2(hk[(r0 + 3) * 513]);
            const ulonglong2* wv = (const ulonglong2*)(ws + k * 48 + c0);
            ulonglong2 p0 = wv[0], p1 = wv[1], p2 = wv[2];   // 3x LDS.128
            ull w0 = p0.x, w1 = p0.y, w2 = p1.x, w3 = p1.y, w4 = p2.x, w5 = p2.y;
            ffma2(acc[0][0], A0, w0); ffma2(acc[0][1], A0, w1); ffma2(acc[0][2], A0, w2);
            ffma2(acc[0][3], A0, w3); ffma2(acc[0][4], A0, w4); ffma2(acc[0][5], A0, w5);
            ffma2(acc[1][0], A1, w0); ffma2(acc[1][1], A1, w1); ffma2(acc[1][2], A1, w2);
            ffma2(acc[1][3], A1, w3); ffma2(acc[1][4], A1, w4); ffma2(acc[1][5], A1, w5);
            ffma2(acc[2][0], A2, w0); ffma2(acc[2][1], A2, w1); ffma2(acc[2][2], A2, w2);
            ffma2(acc[2][3], A2, w3); ffma2(acc[2][4], A2, w4); ffma2(acc[2][5], A2, w5);
            ffma2(acc[3][0], A3, w0); ffma2(acc[3][1], A3, w1); ffma2(acc[3][2], A3, w2);
            ffma2(acc[3][3], A3, w3); ffma2(acc[3][4], A3, w4); ffma2(acc[3][5], A3, w5);
        }
        float* rpw = rp + wrp * (32 * 49);
#pragma unroll
        for (int i = 0; i < 4; ++i)
#pragma unroll
            for (int q = 0; q < 6; ++q) {
                float2 u = unpk(acc[i][q]);
                rpw[(r0 + i) * 49 + c0 + 2 * q]     = u.x;
                rpw[(r0 + i) * 49 + c0 + 2 * q + 1] = u.y;
            }
        __syncthreads();

        // reduce 8 partials + gates + state update
        float* hdst = g_h[(t + 1) & 1];
        float* yout = isLast ? dout : (float*)g_y;
#pragma unroll
        for (int q = 0; q < 2; ++q) {
            int idx = tid + q * 256;
            int b = idx >> 4, c = idx & 15;
            int gb = b0g + b, gc = c0g + c;
            int base = b * 49;
            float rz = brs[c], rr = brs[16 + c], rh = brs[32 + c];
#pragma unroll
            for (int w = 0; w < 8; ++w) {
                int o = w * 1568 + base;
                rz += rp[o + c];
                rr += rp[o + 16 + c];
                rh += rp[o + 32 + c];
            }
            float z = 1.0f / (1.0f + expf(-(pz[q] + rz)));
            float r = 1.0f / (1.0f + expf(-(pr[q] + rr)));
            float hh = tanhf(ph[q] + r * rh);
            float hold = hs[b * 513 + gc];
            float hn = z * hold + (1.0f - z) * hh;
            hdst[(size_t)gb * HH + gc] = hn;
            yout[((size_t)gb * TT + t) * HH + gc] = hn;
        }

        __threadfence();
        __syncthreads();
        if (tid == 0) atomicAdd(&g_bar[g], 1u);
    }
}

__global__ void copy_h_k(float* dout, int out_size) {
    int i = blockIdx.x * blockDim.x + threadIdx.x;
    size_t off = (size_t)BB * TT * HH;
    if (i < BB * HH && (off + i) < (size_t)out_size)
        dout[off + i] = g_h[0][i];
}

extern "C" void kernel_launch(void* const* d_in, const int* in_sizes, int n_in,
                              void* d_out, int out_size) {
    const float* x        = (const float*)d_in[0];
    const float* kernels  = (const float*)d_in[1];
    const float* rkernels = (const float*)d_in[2];
    const float* biases   = (const float*)d_in[3];
    float* out = (float*)d_out;

    cudaFuncSetAttribute(gru_layer_k, cudaFuncAttributeMaxDynamicSharedMemorySize,
                         SMEM_FLOATS * (int)sizeof(float));
    init_k<<<(BB * HH + 255) / 256, 256>>>();

    dim3 pgrid(H3 / 64, (BB * TT) / 128);
    for (int l = 0; l < 3; ++l) {
        proj_k<<<pgrid, 256>>>(x, kernels + (size_t)l * HH * H3,
                               biases + (size_t)l * 2 * H3, l > 0);
        gru_layer_k<<<128, 256, SMEM_FLOATS * (int)sizeof(float)>>>(
            rkernels + (size_t)l * HH * H3,
            biases + (size_t)l * 2 * H3 + H3,
            out, l, (l == 2) ? 1 : 0);
    }
    copy_h_k<<<(BB * HH + 255) / 256, 256>>>(out, out_size);
}

// round 8
// speedup vs baseline: 1.7222x; 1.0407x over previous
#include <cuda_runtime.h>
#include <math.h>

#define BB 128
#define TT 256
#define HH 512
#define H3 1536
typedef unsigned long long ull;

__device__ __forceinline__ ull dup2(float x) {
    ull r; asm("mov.b64 %0, {%1, %1};" : "=l"(r) : "f"(x)); return r;
}
__device__ __forceinline__ void ffma2(ull& d, ull a, ull b) {
    asm("fma.rn.f32x2 %0, %1, %2, %0;" : "+l"(d) : "l"(a), "l"(b));
}
__device__ __forceinline__ float2 unpk(ull v) {
    float2 f; asm("mov.b64 {%0, %1}, %2;" : "=f"(f.x), "=f"(f.y) : "l"(v)); return f;
}

__device__ float g_xp[(size_t)BB * TT * H3];
__device__ float g_y [(size_t)BB * TT * HH];
__device__ float g_h [2][BB * HH];
__device__ unsigned g_bar[4];
__device__ unsigned g_dummy;

__global__ void init_k() {
    int i = blockIdx.x * blockDim.x + threadIdx.x;
    if (i < BB * HH) g_h[0][i] = 0.0f;
    if (i < 4) g_bar[i] = 0u;
}

// tiny deterministic dummy (shifts ncu's -s 5 window onto gru_layer_k)
__global__ void dummy_k() { if (threadIdx.x == 0) g_dummy = 0u; }

// ---- proj: g_xp = Ain @ Wk + b0 (FFMA2, tile 128x64, BK=16, 4 CTA/SM) ------
__global__ void __launch_bounds__(256, 4) proj_k(const float* __restrict__ xin,
                                                 const float* __restrict__ Wk,
                                                 const float* __restrict__ bias,
                                                 int useY)
{
    const float* Ain = useY ? (const float*)g_y : xin;
    __shared__ float As[16 * 128];
    __shared__ float Bs[16 * 64];
    const int tid = threadIdx.x;
    const int m0 = blockIdx.y * 128, n0 = blockIdx.x * 64;
    const int tx = tid & 15, ty = tid >> 4;
    const int my = ty * 8;
    const int mA = tid >> 1, kA = (tid & 1) * 8;
    const int kB = tid >> 4, nB = (tid & 15) * 4;
    const float* aptr = Ain + (size_t)(m0 + mA) * HH + kA;
    const float* bptr = Wk + (size_t)kB * H3 + n0 + nB;

    ull acc[4][4];
#pragma unroll
    for (int p = 0; p < 4; ++p)
#pragma unroll
        for (int j = 0; j < 4; ++j) acc[p][j] = 0ull;

    for (int kt = 0; kt < HH / 16; ++kt) {
        float4 av0 = *(const float4*)(aptr + kt * 16);
        float4 av1 = *(const float4*)(aptr + kt * 16 + 4);
        float4 bv  = *(const float4*)(bptr + (size_t)(kt * 16) * H3);
        __syncthreads();
        As[(kA + 0) * 128 + mA] = av0.x; As[(kA + 1) * 128 + mA] = av0.y;
        As[(kA + 2) * 128 + mA] = av0.z; As[(kA + 3) * 128 + mA] = av0.w;
        As[(kA + 4) * 128 + mA] = av1.x; As[(kA + 5) * 128 + mA] = av1.y;
        As[(kA + 6) * 128 + mA] = av1.z; As[(kA + 7) * 128 + mA] = av1.w;
        *(float4*)&Bs[kB * 64 + nB] = bv;
        __syncthreads();
#pragma unroll
        for (int k = 0; k < 16; ++k) {
            const ull* ap = (const ull*)(As + k * 128 + my);
            ull A0 = ap[0], A1 = ap[1], A2 = ap[2], A3 = ap[3];
            float4 w4 = *(const float4*)(Bs + k * 64 + tx * 4);
            ull W0 = dup2(w4.x), W1 = dup2(w4.y), W2 = dup2(w4.z), W3 = dup2(w4.w);
            ffma2(acc[0][0], A0, W0); ffma2(acc[0][1], A0, W1);
            ffma2(acc[0][2], A0, W2); ffma2(acc[0][3], A0, W3);
            ffma2(acc[1][0], A1, W0); ffma2(acc[1][1], A1, W1);
            ffma2(acc[1][2], A1, W2); ffma2(acc[1][3], A1, W3);
            ffma2(acc[2][0], A2, W0); ffma2(acc[2][1], A2, W1);
            ffma2(acc[2][2], A2, W2); ffma2(acc[2][3], A2, W3);
            ffma2(acc[3][0], A3, W0); ffma2(acc[3][1], A3, W1);
            ffma2(acc[3][2], A3, W2); ffma2(acc[3][3], A3, W3);
        }
    }
    float4 b4 = *(const float4*)&bias[n0 + tx * 4];
    float bb[4] = {b4.x, b4.y, b4.z, b4.w};
#pragma unroll
    for (int p = 0; p < 4; ++p) {
        float2 u0 = unpk(acc[p][0]), u1 = unpk(acc[p][1]);
        float2 u2 = unpk(acc[p][2]), u3 = unpk(acc[p][3]);
        int rlo = m0 + my + 2 * p;
        float4 o0 = {u0.x + bb[0], u1.x + bb[1], u2.x + bb[2], u3.x + bb[3]};
        float4 o1 = {u0.y + bb[0], u1.y + bb[1], u2.y + bb[2], u3.y + bb[3]};
        *(float4*)&g_xp[(size_t)rlo * H3 + n0 + tx * 4] = o0;
        *(float4*)&g_xp[(size_t)(rlo + 1) * H3 + n0 + tx * 4] = o1;
    }
}

// ---- gru: 8-warp split-K FFMA2; stride-516 hs => STS.128 staging, rows +8 ----
#define HSTRIDE 516
#define SM_WS   (512 * 48)
#define SM_HS   (32 * HSTRIDE)
#define SM_RP   (8 * 32 * 49)
#define SMEM_FLOATS (SM_WS + SM_HS + SM_RP + 48)

__global__ void __launch_bounds__(256, 1) gru_layer_k(const float* __restrict__ Wu,
                                                      const float* __restrict__ br,
                                                      float* __restrict__ dout,
                                                      int layer, int isLast)
{
    extern __shared__ float sm[];
    float* ws  = sm;              // [k][j], j = gate*16+cc
    float* hs  = ws + SM_WS;      // [b][k], stride 516 (16B-aligned rows)
    float* rp  = hs + SM_HS;      // [warp][b][j], stride 49
    float* brs = rp + SM_RP;

    const int tid = threadIdx.x;
    const int g   = blockIdx.x >> 5;
    const int hg  = blockIdx.x & 31;
    const int b0g = g * 32, c0g = hg * 16;

    for (int idx = tid; idx < SM_WS; idx += 256) {
        int k = idx / 48, j = idx % 48;
        ws[idx] = Wu[(size_t)k * H3 + (j >> 4) * HH + c0g + (j & 15)];
    }
    for (int j = tid; j < 48; j += 256)
        brs[j] = br[(j >> 4) * HH + c0g + (j & 15)];
    __syncthreads();

    const int wrp = tid >> 5, lane = tid & 31;
    const int rbase = lane & 7;             // rows rbase + 8*i (bank-safe w/ stride 516)
    const int c0 = (lane >> 3) * 12;        // 12 cols / thread (6 f32x2)
    const int kbase = wrp * 64;
    const unsigned layerBase = (unsigned)layer * TT;

    for (int t = 0; t < TT; ++t) {
        // xp prefetch (barrier-independent)
        float pz[2], pr[2], ph[2];
#pragma unroll
        for (int q = 0; q < 2; ++q) {
            int idx = tid + q * 256;
            const float* xb = g_xp + ((size_t)(b0g + (idx >> 4)) * TT + t) * H3
                              + (c0g + (idx & 15));
            pz[q] = __ldcs(xb); pr[q] = __ldcs(xb + HH); ph[q] = __ldcs(xb + 2 * HH);
        }

        unsigned target = 32u * (layerBase + (unsigned)t);
        if (tid == 0) { while (*(volatile unsigned*)&g_bar[g] < target) { } }
        __syncthreads();
        __threadfence();

        // stage h[32][512]: LDG.128 -> STS.128, conflict-free, full coverage
        const float* hsrc = g_h[t & 1];
#pragma unroll
        for (int u = 0; u < 16; ++u) {
            int it = tid + u * 256;
            int b = it >> 7, kq = it & 127;
            float4 v = __ldcg((const float4*)&hsrc[(size_t)(b0g + b) * HH + (kq << 2)]);
            *(float4*)&hs[b * HSTRIDE + (kq << 2)] = v;
        }
        __syncthreads();

        // split-K GEMM: this warp's 64-k slice of rec[32][48]
        ull acc[4][6];
#pragma unroll
        for (int i = 0; i < 4; ++i)
#pragma unroll
            for (int q = 0; q < 6; ++q) acc[i][q] = 0ull;
#pragma unroll 4
        for (int kk = 0; kk < 64; ++kk) {
            int k = kbase + kk;
            const float* hk = hs + k;
            ull A0 = dup2(hk[(rbase +  0) * HSTRIDE]);
            ull A1 = dup2(hk[(rbase +  8) * HSTRIDE]);
            ull A2 = dup2(hk[(rbase + 16) * HSTRIDE]);
            ull A3 = dup2(hk[(rbase + 24) * HSTRIDE]);
            const ulonglong2* wv = (const ulonglong2*)(ws + k * 48 + c0);
            ulonglong2 p0 = wv[0], p1 = wv[1], p2 = wv[2];   // 3x LDS.128
            ull w0 = p0.x, w1 = p0.y, w2 = p1.x, w3 = p1.y, w4 = p2.x, w5 = p2.y;
            ffma2(acc[0][0], A0, w0); ffma2(acc[0][1], A0, w1); ffma2(acc[0][2], A0, w2);
            ffma2(acc[0][3], A0, w3); ffma2(acc[0][4], A0, w4); ffma2(acc[0][5], A0, w5);
            ffma2(acc[1][0], A1, w0); ffma2(acc[1][1], A1, w1); ffma2(acc[1][2], A1, w2);
            ffma2(acc[1][3], A1, w3); ffma2(acc[1][4], A1, w4); ffma2(acc[1][5], A1, w5);
            ffma2(acc[2][0], A2, w0); ffma2(acc[2][1], A2, w1); ffma2(acc[2][2], A2, w2);
            ffma2(acc[2][3], A2, w3); ffma2(acc[2][4], A2, w4); ffma2(acc[2][5], A2, w5);
            ffma2(acc[3][0], A3, w0); ffma2(acc[3][1], A3, w1); ffma2(acc[3][2], A3, w2);
            ffma2(acc[3][3], A3, w3); ffma2(acc[3][4], A3, w4); ffma2(acc[3][5], A3, w5);
        }
        float* rpw = rp + wrp * (32 * 49);
#pragma unroll
        for (int i = 0; i < 4; ++i) {
            int row = rbase + 8 * i;
#pragma unroll
            for (int q = 0; q < 6; ++q) {
                float2 u = unpk(acc[i][q]);
                rpw[row * 49 + c0 + 2 * q]     = u.x;
                rpw[row * 49 + c0 + 2 * q + 1] = u.y;
            }
        }
        __syncthreads();

        // reduce 8 partials + gates + state update
        float* hdst = g_h[(t + 1) & 1];
        float* yout = isLast ? dout : (float*)g_y;
#pragma unroll
        for (int q = 0; q < 2; ++q) {
            int idx = tid + q * 256;
            int b = idx >> 4, c = idx & 15;
            int gb = b0g + b, gc = c0g + c;
            int base = b * 49;
            float rz = brs[c], rr = brs[16 + c], rh = brs[32 + c];
#pragma unroll
            for (int w = 0; w < 8; ++w) {
                int o = w * 1568 + base;
                rz += rp[o + c];
                rr += rp[o + 16 + c];
                rh += rp[o + 32 + c];
            }
            float z = 1.0f / (1.0f + expf(-(pz[q] + rz)));
            float r = 1.0f / (1.0f + expf(-(pr[q] + rr)));
            float hh = tanhf(ph[q] + r * rh);
            float hold = hs[b * HSTRIDE + gc];
            float hn = z * hold + (1.0f - z) * hh;
            hdst[(size_t)gb * HH + gc] = hn;
            yout[((size_t)gb * TT + t) * HH + gc] = hn;
        }

        __threadfence();
        __syncthreads();
        if (tid == 0) atomicAdd(&g_bar[g], 1u);
    }
}

__global__ void copy_h_k(float* dout, int out_size) {
    int i = blockIdx.x * blockDim.x + threadIdx.x;
    size_t off = (size_t)BB * TT * HH;
    if (i < BB * HH && (off + i) < (size_t)out_size)
        dout[off + i] = g_h[0][i];
}

extern "C" void kernel_launch(void* const* d_in, const int* in_sizes, int n_in,
                              void* d_out, int out_size) {
    const float* x        = (const float*)d_in[0];
    const float* kernels  = (const float*)d_in[1];
    const float* rkernels = (const float*)d_in[2];
    const float* biases   = (const float*)d_in[3];
    float* out = (float*)d_out;

    cudaFuncSetAttribute(gru_layer_k, cudaFuncAttributeMaxDynamicSharedMemorySize,
                         SMEM_FLOATS * (int)sizeof(float));
    init_k<<<(BB * HH + 255) / 256, 256>>>();
    // launches 1-3: dummies so ncu (-s 5 -c 1) captures gru_layer_k at index 5
    dummy_k<<<1, 32>>>();
    dummy_k<<<1, 32>>>();
    dummy_k<<<1, 32>>>();

    dim3 pgrid(H3 / 64, (BB * TT) / 128);
    for (int l = 0; l < 3; ++l) {
        proj_k<<<pgrid, 256>>>(x, kernels + (size_t)l * HH * H3,
                               biases + (size_t)l * 2 * H3, l > 0);
        gru_layer_k<<<128, 256, SMEM_FLOATS * (int)sizeof(float)>>>(
            rkernels + (size_t)l * HH * H3,
            biases + (size_t)l * 2 * H3 + H3,
            out, l, (l == 2) ? 1 : 0);
    }
    copy_h_k<<<(BB * HH + 255) / 256, 256>>>(out, out_size);
}

// round 9
// speedup vs baseline: 1.8751x; 1.0888x over previous
#include <cuda_runtime.h>
#include <math.h>

#define BB 128
#define TT 256
#define HH 512
#define H3 1536
typedef unsigned long long ull;

__device__ __forceinline__ ull dup2(float x) {
    ull r; asm("mov.b64 %0, {%1, %1};" : "=l"(r) : "f"(x)); return r;
}
__device__ __forceinline__ void ffma2(ull& d, ull a, ull b) {
    asm("fma.rn.f32x2 %0, %1, %2, %0;" : "+l"(d) : "l"(a), "l"(b));
}
__device__ __forceinline__ float2 unpk(ull v) {
    float2 f; asm("mov.b64 {%0, %1}, %2;" : "=f"(f.x), "=f"(f.y) : "l"(v)); return f;
}

__device__ float g_xp[(size_t)BB * TT * H3];
__device__ float g_y [(size_t)BB * TT * HH];
__device__ float g_h [2][BB * HH];
__device__ unsigned g_bar2[4][8];      // spread arrival counters (8 per batch group)
__device__ unsigned g_dummy;

__global__ void init_k() {
    int i = blockIdx.x * blockDim.x + threadIdx.x;
    if (i < BB * HH) g_h[0][i] = 0.0f;
    if (i < 32) ((unsigned*)g_bar2)[i] = 0u;
}

// one dummy so ncu's fixed -s 5 window lands on gru_layer_k (harness injects ~2)
__global__ void dummy_k() { if (threadIdx.x == 0) g_dummy = 0u; }

// ---- proj: g_xp = Ain @ Wk + b0 (FFMA2, tile 128x64, BK=16, 4 CTA/SM) ------
__global__ void __launch_bounds__(256, 4) proj_k(const float* __restrict__ xin,
                                                 const float* __restrict__ Wk,
                                                 const float* __restrict__ bias,
                                                 int useY)
{
    const float* Ain = useY ? (const float*)g_y : xin;
    __shared__ float As[16 * 128];
    __shared__ float Bs[16 * 64];
    const int tid = threadIdx.x;
    const int m0 = blockIdx.y * 128, n0 = blockIdx.x * 64;
    const int tx = tid & 15, ty = tid >> 4;
    const int my = ty * 8;
    const int mA = tid >> 1, kA = (tid & 1) * 8;
    const int kB = tid >> 4, nB = (tid & 15) * 4;
    const float* aptr = Ain + (size_t)(m0 + mA) * HH + kA;
    const float* bptr = Wk + (size_t)kB * H3 + n0 + nB;

    ull acc[4][4];
#pragma unroll
    for (int p = 0; p < 4; ++p)
#pragma unroll
        for (int j = 0; j < 4; ++j) acc[p][j] = 0ull;

    for (int kt = 0; kt < HH / 16; ++kt) {
        float4 av0 = *(const float4*)(aptr + kt * 16);
        float4 av1 = *(const float4*)(aptr + kt * 16 + 4);
        float4 bv  = *(const float4*)(bptr + (size_t)(kt * 16) * H3);
        __syncthreads();
        As[(kA + 0) * 128 + mA] = av0.x; As[(kA + 1) * 128 + mA] = av0.y;
        As[(kA + 2) * 128 + mA] = av0.z; As[(kA + 3) * 128 + mA] = av0.w;
        As[(kA + 4) * 128 + mA] = av1.x; As[(kA + 5) * 128 + mA] = av1.y;
        As[(kA + 6) * 128 + mA] = av1.z; As[(kA + 7) * 128 + mA] = av1.w;
        *(float4*)&Bs[kB * 64 + nB] = bv;
        __syncthreads();
#pragma unroll
        for (int k = 0; k < 16; ++k) {
            const ulonglong2* ap = (const ulonglong2*)(As + k * 128 + my);
            ulonglong2 q0 = ap[0], q1 = ap[1];          // 2x LDS.128 (was 4x LDS.64)
            ull A0 = q0.x, A1 = q0.y, A2 = q1.x, A3 = q1.y;
            float4 w4 = *(const float4*)(Bs + k * 64 + tx * 4);
            ull W0 = dup2(w4.x), W1 = dup2(w4.y), W2 = dup2(w4.z), W3 = dup2(w4.w);
            ffma2(acc[0][0], A0, W0); ffma2(acc[0][1], A0, W1);
            ffma2(acc[0][2], A0, W2); ffma2(acc[0][3], A0, W3);
            ffma2(acc[1][0], A1, W0); ffma2(acc[1][1], A1, W1);
            ffma2(acc[1][2], A1, W2); ffma2(acc[1][3], A1, W3);
            ffma2(acc[2][0], A2, W0); ffma2(acc[2][1], A2, W1);
            ffma2(acc[2][2], A2, W2); ffma2(acc[2][3], A2, W3);
            ffma2(acc[3][0], A3, W0); ffma2(acc[3][1], A3, W1);
            ffma2(acc[3][2], A3, W2); ffma2(acc[3][3], A3, W3);
        }
    }
    float4 b4 = *(const float4*)&bias[n0 + tx * 4];
    float bb[4] = {b4.x, b4.y, b4.z, b4.w};
#pragma unroll
    for (int p = 0; p < 4; ++p) {
        float2 u0 = unpk(acc[p][0]), u1 = unpk(acc[p][1]);
        float2 u2 = unpk(acc[p][2]), u3 = unpk(acc[p][3]);
        int rlo = m0 + my + 2 * p;
        float4 o0 = {u0.x + bb[0], u1.x + bb[1], u2.x + bb[2], u3.x + bb[3]};
        float4 o1 = {u0.y + bb[0], u1.y + bb[1], u2.y + bb[2], u3.y + bb[3]};
        *(float4*)&g_xp[(size_t)rlo * H3 + n0 + tx * 4] = o0;
        *(float4*)&g_xp[(size_t)(rlo + 1) * H3 + n0 + tx * 4] = o1;
    }
}

// ---- gru: 8-warp split-K FFMA2, spread barrier + release/acquire -------------
#define HSTRIDE 516
#define SM_WS   (512 * 48)
#define SM_HS   (32 * HSTRIDE)
#define SM_RP   (8 * 32 * 49)
#define SMEM_FLOATS (SM_WS + SM_HS + SM_RP + 48)

__global__ void __launch_bounds__(256, 1) gru_layer_k(const float* __restrict__ Wu,
                                                      const float* __restrict__ br,
                                                      float* __restrict__ dout,
                                                      int layer, int isLast)
{
    extern __shared__ float sm[];
    float* ws  = sm;              // [k][j], j = gate*16+cc
    float* hs  = ws + SM_WS;      // [b][k], stride 516
    float* rp  = hs + SM_HS;      // [warp][b][j], stride 49
    float* brs = rp + SM_RP;

    const int tid = threadIdx.x;
    const int g   = blockIdx.x >> 5;
    const int hg  = blockIdx.x & 31;
    const int b0g = g * 32, c0g = hg * 16;
    unsigned* myCnt = &g_bar2[g][hg & 7];

    for (int idx = tid; idx < SM_WS; idx += 256) {
        int k = idx / 48, j = idx % 48;
        ws[idx] = Wu[(size_t)k * H3 + (j >> 4) * HH + c0g + (j & 15)];
    }
    for (int j = tid; j < 48; j += 256)
        brs[j] = br[(j >> 4) * HH + c0g + (j & 15)];
    __syncthreads();

    const int wrp = tid >> 5, lane = tid & 31;
    const int rbase = lane & 7;
    const int c0 = (lane >> 3) * 12;
    const int kbase = wrp * 64;
    const unsigned layerBase = (unsigned)layer * TT;

    for (int t = 0; t < TT; ++t) {
        // xp prefetch (barrier-independent)
        float pz[2], pr[2], ph[2];
#pragma unroll
        for (int q = 0; q < 2; ++q) {
            int idx = tid + q * 256;
            const float* xb = g_xp + ((size_t)(b0g + (idx >> 4)) * TT + t) * H3
                              + (c0g + (idx & 15));
            pz[q] = __ldcs(xb); pr[q] = __ldcs(xb + HH); ph[q] = __ldcs(xb + 2 * HH);
        }

        // spread-counter barrier: 8 lanes read 8 counters, butterfly-sum
        unsigned target = 32u * (layerBase + (unsigned)t);
        if (tid < 8) {
            const unsigned* cp = &g_bar2[g][tid];
            for (;;) {
                unsigned v;
                asm volatile("ld.acquire.gpu.global.u32 %0, [%1];" : "=r"(v) : "l"(cp));
                v += __shfl_xor_sync(0xffu, v, 1);
                v += __shfl_xor_sync(0xffu, v, 2);
                v += __shfl_xor_sync(0xffu, v, 4);
                if (v >= target) break;
            }
        }
        __syncthreads();

        // stage h[32][512]: LDG.128 -> STS.128, conflict-free
        const float* hsrc = g_h[t & 1];
#pragma unroll
        for (int u = 0; u < 16; ++u) {
            int it = tid + u * 256;
            int b = it >> 7, kq = it & 127;
            float4 v = __ldcg((const float4*)&hsrc[(size_t)(b0g + b) * HH + (kq << 2)]);
            *(float4*)&hs[b * HSTRIDE + (kq << 2)] = v;
        }
        __syncthreads();

        // split-K GEMM: this warp's 64-k slice of rec[32][48]
        ull acc[4][6];
#pragma unroll
        for (int i = 0; i < 4; ++i)
#pragma unroll
            for (int q = 0; q < 6; ++q) acc[i][q] = 0ull;
#pragma unroll 4
        for (int kk = 0; kk < 64; ++kk) {
            int k = kbase + kk;
            const float* hk = hs + k;
            ull A0 = dup2(hk[(rbase +  0) * HSTRIDE]);
            ull A1 = dup2(hk[(rbase +  8) * HSTRIDE]);
            ull A2 = dup2(hk[(rbase + 16) * HSTRIDE]);
            ull A3 = dup2(hk[(rbase + 24) * HSTRIDE]);
            const ulonglong2* wv = (const ulonglong2*)(ws + k * 48 + c0);
            ulonglong2 p0 = wv[0], p1 = wv[1], p2 = wv[2];
            ull w0 = p0.x, w1 = p0.y, w2 = p1.x, w3 = p1.y, w4 = p2.x, w5 = p2.y;
            ffma2(acc[0][0], A0, w0); ffma2(acc[0][1], A0, w1); ffma2(acc[0][2], A0, w2);
            ffma2(acc[0][3], A0, w3); ffma2(acc[0][4], A0, w4); ffma2(acc[0][5], A0, w5);
            ffma2(acc[1][0], A1, w0); ffma2(acc[1][1], A1, w1); ffma2(acc[1][2], A1, w2);
            ffma2(acc[1][3], A1, w3); ffma2(acc[1][4], A1, w4); ffma2(acc[1][5], A1, w5);
            ffma2(acc[2][0], A2, w0); ffma2(acc[2][1], A2, w1); ffma2(acc[2][2], A2, w2);
            ffma2(acc[2][3], A2, w3); ffma2(acc[2][4], A2, w4); ffma2(acc[2][5], A2, w5);
            ffma2(acc[3][0], A3, w0); ffma2(acc[3][1], A3, w1); ffma2(acc[3][2], A3, w2);
            ffma2(acc[3][3], A3, w3); ffma2(acc[3][4], A3, w4); ffma2(acc[3][5], A3, w5);
        }
        float* rpw = rp + wrp * (32 * 49);
#pragma unroll
        for (int i = 0; i < 4; ++i) {
            int row = rbase + 8 * i;
#pragma unroll
            for (int q = 0; q < 6; ++q) {
                float2 u = unpk(acc[i][q]);
                rpw[row * 49 + c0 + 2 * q]     = u.x;
                rpw[row * 49 + c0 + 2 * q + 1] = u.y;
            }
        }
        __syncthreads();

        // reduce 8 partials + gates + state update
        float* hdst = g_h[(t + 1) & 1];
        float* yout = isLast ? dout : (float*)g_y;
#pragma unroll
        for (int q = 0; q < 2; ++q) {
            int idx = tid + q * 256;
            int b = idx >> 4, c = idx & 15;
            int gb = b0g + b, gc = c0g + c;
            int base = b * 49;
            float rz = brs[c], rr = brs[16 + c], rh = brs[32 + c];
#pragma unroll
            for (int w = 0; w < 8; ++w) {
                int o = w * 1568 + base;
                rz += rp[o + c];
                rr += rp[o + 16 + c];
                rh += rp[o + 32 + c];
            }
            float z = 1.0f / (1.0f + expf(-(pz[q] + rz)));
            float r = 1.0f / (1.0f + expf(-(pr[q] + rr)));
            float hh = tanhf(ph[q] + r * rh);
            float hold = hs[b * HSTRIDE + gc];
            float hn = z * hold + (1.0f - z) * hh;
            hdst[(size_t)gb * HH + gc] = hn;
            yout[((size_t)gb * TT + t) * HH + gc] = hn;
        }

        // arrive: release-add to this CTA's spread counter (no full fence)
        __syncthreads();
        if (tid == 0)
            asm volatile("red.release.gpu.global.add.u32 [%0], %1;"
                         :: "l"(myCnt), "r"(1u) : "memory");
    }
}

__global__ void copy_h_k(float* dout, int out_size) {
    int i = blockIdx.x * blockDim.x + threadIdx.x;
    size_t off = (size_t)BB * TT * HH;
    if (i < BB * HH && (off + i) < (size_t)out_size)
        dout[off + i] = g_h[0][i];
}

extern "C" void kernel_launch(void* const* d_in, const int* in_sizes, int n_in,
                              void* d_out, int out_size) {
    const float* x        = (const float*)d_in[0];
    const float* kernels  = (const float*)d_in[1];
    const float* rkernels = (const float*)d_in[2];
    const float* biases   = (const float*)d_in[3];
    float* out = (float*)d_out;

    cudaFuncSetAttribute(gru_layer_k, cudaFuncAttributeMaxDynamicSharedMemorySize,
                         SMEM_FLOATS * (int)sizeof(float));
    init_k<<<(BB * HH + 255) / 256, 256>>>();
    dummy_k<<<1, 32>>>();   // single pad: gru_layer_k should land at ncu index 5

    dim3 pgrid(H3 / 64, (BB * TT) / 128);
    for (int l = 0; l < 3; ++l) {
        proj_k<<<pgrid, 256>>>(x, kernels + (size_t)l * HH * H3,
                               biases + (size_t)l * 2 * H3, l > 0);
        gru_layer_k<<<128, 256, SMEM_FLOATS * (int)sizeof(float)>>>(
            rkernels + (size_t)l * HH * H3,
            biases + (size_t)l * 2 * H3 + H3,
            out, l, (l == 2) ? 1 : 0);
    }
    copy_h_k<<<(BB * HH + 255) / 256, 256>>>(out, out_size);
}